// round 1
// baseline (speedup 1.0000x reference)
#include <cuda_runtime.h>
#include <math.h>

#define BB 4
#define LL 4096
#define DD 1024
#define DI_ 4096
#define MM 8
#define ROWS (BB*LL)          /* 16384 */
#define THRG 0.5f
#define EPSLN 1e-6f

/* ---------------- scratch (device globals; no allocations allowed) -------- */
__device__ float g_bufA[ROWS*DD];      /* 64 MB  */
__device__ float g_bufB[ROWS*DD];      /* 64 MB  */
__device__ float g_up[ (size_t)ROWS*DI_ ]; /* 256 MB */
__device__ float g_acc[ROWS*DD];       /* 64 MB  */
__device__ float g_cum[ROWS];
__device__ float g_scores[ROWS*MM];
__device__ float g_mean[ROWS];
__device__ float g_rstd[ROWS];
__device__ int   g_flag[ROWS];
__device__ float g_colmax[BB*MM];
__device__ float g_colsum[BB*MM];
__device__ float g_mem[BB*MM*DD];
__device__ float g_mA[BB*MM*DD];

/* ---------------- reduction helpers -------------------------------------- */
__device__ __forceinline__ float warpRedSum(float v){
#pragma unroll
    for(int o=16;o>0;o>>=1) v += __shfl_xor_sync(0xffffffffu, v, o);
    return v;
}
__device__ __forceinline__ float warpRedMax(float v){
#pragma unroll
    for(int o=16;o>0;o>>=1) v = fmaxf(v, __shfl_xor_sync(0xffffffffu, v, o));
    return v;
}
/* block of 256 threads */
__device__ float blockRedSum(float v, float* sh){
    int lane = threadIdx.x & 31, w = threadIdx.x >> 5;
    v = warpRedSum(v);
    __syncthreads();
    if(lane==0) sh[w] = v;
    __syncthreads();
    if(threadIdx.x==0){
        float r = sh[0];
#pragma unroll
        for(int i=1;i<8;i++) r += sh[i];
        sh[0] = r;
    }
    __syncthreads();
    return sh[0];
}
__device__ float blockRedMax(float v, float* sh){
    int lane = threadIdx.x & 31, w = threadIdx.x >> 5;
    v = warpRedMax(v);
    __syncthreads();
    if(lane==0) sh[w] = v;
    __syncthreads();
    if(threadIdx.x==0){
        float r = sh[0];
#pragma unroll
        for(int i=1;i<8;i++) r = fmaxf(r, sh[i]);
        sh[0] = r;
    }
    __syncthreads();
    return sh[0];
}

/* ------------- per-row LN stats + normalized entropy of hidden ------------ */
__global__ void __launch_bounds__(256) rowstat_kernel(const float* __restrict__ X){
    __shared__ float sh[8];
    int row = blockIdx.x;
    const float4 x4 = *((const float4*)(X + (size_t)row*DD) + threadIdx.x);
    float s = x4.x + x4.y + x4.z + x4.w;
    float mean = blockRedSum(s, sh) * (1.0f/DD);
    float sq = x4.x*x4.x + x4.y*x4.y + x4.z*x4.z + x4.w*x4.w;
    float var = blockRedSum(sq, sh) * (1.0f/DD) - mean*mean;
    float rstd = rsqrtf(fmaxf(var, 0.0f) + EPSLN);
    float mx = fmaxf(fmaxf(x4.x,x4.y), fmaxf(x4.z,x4.w));
    mx = blockRedMax(mx, sh);
    float e0=expf(x4.x-mx), e1=expf(x4.y-mx), e2=expf(x4.z-mx), e3=expf(x4.w-mx);
    float se  = e0+e1+e2+e3;
    float sxe = e0*x4.x + e1*x4.y + e2*x4.z + e3*x4.w;
    se  = blockRedSum(se, sh);
    sxe = blockRedSum(sxe, sh);
    if(threadIdx.x==0){
        g_mean[row]=mean; g_rstd[row]=rstd;
        float logZ = mx + logf(se);
        float ent = (logZ - sxe/se) * (1.0f/logf((float)DD));
        g_flag[row] = (ent > THRG) ? 1 : 0;
    }
}

/* ------------- up GEMM: gelu(LN(hidden) @ W_up + b_up) -> g_up ------------ */
__global__ void __launch_bounds__(256) gemm_up_kernel(
    const float* __restrict__ X, const float* __restrict__ W,
    const float* __restrict__ bias,
    const float* __restrict__ g1, const float* __restrict__ b1)
{
    const int K = DD, N = DI_;
    __shared__ float As[16][128];
    __shared__ float Bs[16][128];
    int tid = threadIdx.x;
    int mBase = blockIdx.y*128, nBase = blockIdx.x*128;
    int tx = tid & 15, ty = tid >> 4;
    float acc[8][8];
#pragma unroll
    for(int i=0;i<8;i++)
#pragma unroll
        for(int j=0;j<8;j++) acc[i][j]=0.0f;

    for(int k0=0;k0<K;k0+=16){
#pragma unroll
        for(int i=0;i<2;i++){
            int f = tid + i*256;
            int r = f>>2, c4 = f&3;
            float4 a = *(const float4*)(X + (size_t)(mBase+r)*K + k0 + (c4<<2));
            float mu = g_mean[mBase+r], rs = g_rstd[mBase+r];
            float va[4] = {a.x,a.y,a.z,a.w};
#pragma unroll
            for(int j=0;j<4;j++){
                int kk=(c4<<2)+j;
                As[kk][r] = (va[j]-mu)*rs*__ldg(&g1[k0+kk]) + __ldg(&b1[k0+kk]);
            }
        }
#pragma unroll
        for(int i=0;i<2;i++){
            int f = tid + i*256;
            int kr = f>>5, c4 = f&31;
            *(float4*)(&Bs[kr][c4<<2]) = *(const float4*)(W + (size_t)(k0+kr)*N + nBase + (c4<<2));
        }
        __syncthreads();
#pragma unroll
        for(int kk=0;kk<16;kk++){
            float4 a0 = *(float4*)&As[kk][ty*8];
            float4 a1 = *(float4*)&As[kk][ty*8+4];
            float4 b0 = *(float4*)&Bs[kk][tx*8];
            float4 b1v= *(float4*)&Bs[kk][tx*8+4];
            float a[8] = {a0.x,a0.y,a0.z,a0.w,a1.x,a1.y,a1.z,a1.w};
            float b[8] = {b0.x,b0.y,b0.z,b0.w,b1v.x,b1v.y,b1v.z,b1v.w};
#pragma unroll
            for(int i=0;i<8;i++)
#pragma unroll
                for(int j=0;j<8;j++) acc[i][j] += a[i]*b[j];
        }
        __syncthreads();
    }
    float4 bv0 = *(const float4*)(bias + nBase + tx*8);
    float4 bv1 = *(const float4*)(bias + nBase + tx*8 + 4);
    const float S2 = 0.70710678118654752440f;
#pragma unroll
    for(int i=0;i<8;i++){
        size_t rb = (size_t)(mBase + ty*8 + i)*N + nBase + tx*8;
        float4 v;
        v.x = acc[i][0]+bv0.x; v.y = acc[i][1]+bv0.y; v.z = acc[i][2]+bv0.z; v.w = acc[i][3]+bv0.w;
        v.x = 0.5f*v.x*(1.0f+erff(v.x*S2)); v.y = 0.5f*v.y*(1.0f+erff(v.y*S2));
        v.z = 0.5f*v.z*(1.0f+erff(v.z*S2)); v.w = 0.5f*v.w*(1.0f+erff(v.w*S2));
        *(float4*)(g_up + rb) = v;
        float4 u;
        u.x = acc[i][4]+bv1.x; u.y = acc[i][5]+bv1.y; u.z = acc[i][6]+bv1.z; u.w = acc[i][7]+bv1.w;
        u.x = 0.5f*u.x*(1.0f+erff(u.x*S2)); u.y = 0.5f*u.y*(1.0f+erff(u.y*S2));
        u.z = 0.5f*u.z*(1.0f+erff(u.z*S2)); u.w = 0.5f*u.w*(1.0f+erff(u.w*S2));
        *(float4*)(g_up + rb + 4) = u;
    }
}

/* ------------- down GEMM: h_new = hidden + g_up @ W_down + b_down --------- */
__global__ void __launch_bounds__(256) gemm_down_kernel(
    const float* __restrict__ W, const float* __restrict__ bias,
    const float* __restrict__ Hin, float* __restrict__ Hout)
{
    const int K = DI_, N = DD;
    __shared__ float As[16][128];
    __shared__ float Bs[16][128];
    int tid = threadIdx.x;
    int mBase = blockIdx.y*128, nBase = blockIdx.x*128;
    int tx = tid & 15, ty = tid >> 4;
    float acc[8][8];
#pragma unroll
    for(int i=0;i<8;i++)
#pragma unroll
        for(int j=0;j<8;j++) acc[i][j]=0.0f;

    for(int k0=0;k0<K;k0+=16){
#pragma unroll
        for(int i=0;i<2;i++){
            int f = tid + i*256;
            int r = f>>2, c4 = f&3;
            float4 a = *(const float4*)(g_up + (size_t)(mBase+r)*K + k0 + (c4<<2));
            float va[4] = {a.x,a.y,a.z,a.w};
#pragma unroll
            for(int j=0;j<4;j++) As[(c4<<2)+j][r] = va[j];
        }
#pragma unroll
        for(int i=0;i<2;i++){
            int f = tid + i*256;
            int kr = f>>5, c4 = f&31;
            *(float4*)(&Bs[kr][c4<<2]) = *(const float4*)(W + (size_t)(k0+kr)*N + nBase + (c4<<2));
        }
        __syncthreads();
#pragma unroll
        for(int kk=0;kk<16;kk++){
            float4 a0 = *(float4*)&As[kk][ty*8];
            float4 a1 = *(float4*)&As[kk][ty*8+4];
            float4 b0 = *(float4*)&Bs[kk][tx*8];
            float4 b1v= *(float4*)&Bs[kk][tx*8+4];
            float a[8] = {a0.x,a0.y,a0.z,a0.w,a1.x,a1.y,a1.z,a1.w};
            float b[8] = {b0.x,b0.y,b0.z,b0.w,b1v.x,b1v.y,b1v.z,b1v.w};
#pragma unroll
            for(int i=0;i<8;i++)
#pragma unroll
                for(int j=0;j<8;j++) acc[i][j] += a[i]*b[j];
        }
        __syncthreads();
    }
    float4 bv0 = *(const float4*)(bias + nBase + tx*8);
    float4 bv1 = *(const float4*)(bias + nBase + tx*8 + 4);
#pragma unroll
    for(int i=0;i<8;i++){
        size_t rb = (size_t)(mBase + ty*8 + i)*N + nBase + tx*8;
        float4 h0 = *(const float4*)(Hin + rb);
        float4 h1 = *(const float4*)(Hin + rb + 4);
        float4 v;
        v.x = acc[i][0]+bv0.x+h0.x; v.y = acc[i][1]+bv0.y+h0.y;
        v.z = acc[i][2]+bv0.z+h0.z; v.w = acc[i][3]+bv0.w+h0.w;
        *(float4*)(Hout + rb) = v;
        float4 u;
        u.x = acc[i][4]+bv1.x+h1.x; u.y = acc[i][5]+bv1.y+h1.y;
        u.z = acc[i][6]+bv1.z+h1.z; u.w = acc[i][7]+bv1.w+h1.w;
        *(float4*)(Hout + rb + 4) = u;
    }
}

/* ------------- scores = h_new @ W_comp + b_comp  [ROWS, 8] ---------------- */
__global__ void __launch_bounds__(256) scores_kernel(const float* __restrict__ H,
    const float* __restrict__ Wc, const float* __restrict__ bc)
{
    __shared__ float sW[DD*9];   /* padded [k][m], 36 KB */
    for(int i=threadIdx.x;i<DD*8;i+=256){ int k=i>>3, m=i&7; sW[k*9+m]=Wc[i]; }
    __syncthreads();
    int warp = threadIdx.x>>5, lane = threadIdx.x&31;
    int row = blockIdx.x*8 + warp;
    const float* hr = H + (size_t)row*DD;
    float acc[8] = {0,0,0,0,0,0,0,0};
    for(int k=lane;k<DD;k+=32){
        float x = hr[k];
#pragma unroll
        for(int m=0;m<8;m++) acc[m] += x*sW[k*9+m];
    }
#pragma unroll
    for(int m=0;m<8;m++) acc[m] = warpRedSum(acc[m]);
    if(lane==0){
#pragma unroll
        for(int m=0;m<8;m++) g_scores[(size_t)row*8+m] = acc[m] + bc[m];
    }
}

/* ------------- column softmax stats over L, zero memory/mA --------------- */
__global__ void __launch_bounds__(256) colstats_kernel(){
    __shared__ float sh[8];
    int c = blockIdx.x; int b = c>>3, m = c&7;
    const float* sc = g_scores + (size_t)b*LL*8 + m;
    float v[16];
#pragma unroll
    for(int i=0;i<16;i++) v[i] = sc[(size_t)(threadIdx.x + i*256)*8];
    float mx = -1e30f;
#pragma unroll
    for(int i=0;i<16;i++) mx = fmaxf(mx, v[i]);
    mx = blockRedMax(mx, sh);
    float se = 0.0f;
#pragma unroll
    for(int i=0;i<16;i++) se += expf(v[i]-mx);
    se = blockRedSum(se, sh);
    if(threadIdx.x==0){ g_colmax[c]=mx; g_colsum[c]=se; }
    float4 z = {0,0,0,0};
    ((float4*)(g_mem + (size_t)c*DD))[threadIdx.x] = z;
    ((float4*)(g_mA  + (size_t)c*DD))[threadIdx.x] = z;
}

/* ------------- memory[b,m,:] += sum_l P[l,m] * h[l,:] --------------------- */
__global__ void __launch_bounds__(256) memacc_kernel(const float* __restrict__ H){
    __shared__ float sp[128*8];
    int b = blockIdx.y; int lb = blockIdx.x*128;
    if(threadIdx.x<128){
        int l = lb + threadIdx.x;
#pragma unroll
        for(int m=0;m<8;m++){
            int c = b*8+m;
            sp[threadIdx.x*8+m] = expf(g_scores[((size_t)b*LL+l)*8+m]-g_colmax[c]) / g_colsum[c];
        }
    }
    __syncthreads();
    float4 acc[8];
#pragma unroll
    for(int m=0;m<8;m++){ acc[m].x=0;acc[m].y=0;acc[m].z=0;acc[m].w=0; }
    const float4* hb = (const float4*)(H + ((size_t)b*LL+lb)*DD) + threadIdx.x;
    for(int l=0;l<128;l++){
        float4 h = hb[(size_t)l*(DD/4)];
#pragma unroll
        for(int m=0;m<8;m++){
            float p = sp[l*8+m];
            acc[m].x += p*h.x; acc[m].y += p*h.y; acc[m].z += p*h.z; acc[m].w += p*h.w;
        }
    }
    int d0 = threadIdx.x*4;
#pragma unroll
    for(int m=0;m<8;m++){
        float* mp = g_mem + ((size_t)b*8+m)*DD + d0;
        atomicAdd(mp+0,acc[m].x); atomicAdd(mp+1,acc[m].y);
        atomicAdd(mp+2,acc[m].z); atomicAdd(mp+3,acc[m].w);
    }
}

/* ------------- mA[b,m,:] = memory[b,m,:] @ W_attn  (k-split + atomics) ---- */
__global__ void __launch_bounds__(256) memattn_kernel(const float* __restrict__ Wa){
    __shared__ float sM[8][256];
    int b  = blockIdx.x;
    int nb = blockIdx.y*256;
    int ks = blockIdx.z*256;
    for(int i=threadIdx.x;i<8*256;i+=256){
        int m=i>>8, k=i&255;
        sM[m][k] = g_mem[((size_t)b*8+m)*DD + ks + k];
    }
    __syncthreads();
    int n = nb + threadIdx.x;
    float acc[8] = {0,0,0,0,0,0,0,0};
    for(int k=0;k<256;k++){
        float w = Wa[(size_t)(ks+k)*DD + n];
#pragma unroll
        for(int m=0;m<8;m++) acc[m] += sM[m][k]*w;
    }
#pragma unroll
    for(int m=0;m<8;m++) atomicAdd(&g_mA[((size_t)b*8+m)*DD+n], acc[m]);
}

/* ------------- h_new += softmax_m(scores) @ mA + b_attn ------------------- */
__global__ void __launch_bounds__(256) ctxattn_kernel(float* __restrict__ H,
    const float* __restrict__ ba)
{
    __shared__ float sMA[8*DD];   /* 32 KB */
    __shared__ float sp[32*8];
    int b = blockIdx.y; int rb = blockIdx.x*32;
    for(int i=threadIdx.x;i<8*DD;i+=256) sMA[i] = g_mA[(size_t)b*8*DD + i];
    if(threadIdx.x<32){
        int l = rb + threadIdx.x;
        float s[8]; float mx = -1e30f;
#pragma unroll
        for(int m=0;m<8;m++){ s[m]=g_scores[((size_t)b*LL+l)*8+m]; mx=fmaxf(mx,s[m]); }
        float se=0.0f;
#pragma unroll
        for(int m=0;m<8;m++){ s[m]=expf(s[m]-mx); se+=s[m]; }
        float inv = 1.0f/se;
#pragma unroll
        for(int m=0;m<8;m++) sp[threadIdx.x*8+m] = s[m]*inv;
    }
    __syncthreads();
    int d0 = threadIdx.x*4;
    float4 bv = *(const float4*)(ba + d0);
    for(int r=0;r<32;r++){
        size_t off = ((size_t)b*LL + rb + r)*DD + d0;
        float4 h = *(float4*)(H + off);
#pragma unroll
        for(int m=0;m<8;m++){
            float p = sp[r*8+m];
            float4 mv = *(const float4*)(&sMA[m*DD + d0]);
            h.x += p*mv.x; h.y += p*mv.y; h.z += p*mv.z; h.w += p*mv.w;
        }
        h.x += bv.x; h.y += bv.y; h.z += bv.z; h.w += bv.w;
        *(float4*)(H + off) = h;
    }
}

/* ------------- gate (entropy) + halting + ACT accumulate ------------------ */
__global__ void __launch_bounds__(256) gate_kernel(float* __restrict__ Hn,
    const float* __restrict__ Hold,
    const float* __restrict__ Wh, const float* __restrict__ bh)
{
    __shared__ float sh[8];
    int row = blockIdx.x;
    int upd = g_flag[row];
    size_t off = (size_t)row*DD + threadIdx.x*4;
    float4 v;
    if(upd){
        v = *(const float4*)(Hn + off);
    } else {
        v = *(const float4*)(Hold + off);
        *(float4*)(Hn + off) = v;
    }
    float4 w4 = *(const float4*)(Wh + threadIdx.x*4);
    float d = v.x*w4.x + v.y*w4.y + v.z*w4.z + v.w*w4.w;
    d = blockRedSum(d, sh);
    float p = 1.0f/(1.0f + expf(-(d + bh[0])));
    float cum = g_cum[row];
    float w = p*(1.0f - cum);
    float4 a = *(float4*)(g_acc + off);
    a.x += w*v.x; a.y += w*v.y; a.z += w*v.z; a.w += w*v.w;
    *(float4*)(g_acc + off) = a;
    if(threadIdx.x==0) g_cum[row] = cum + w;
}

/* ------------- out = LN(acc + (1-cum)*hidden; g2,b2) ---------------------- */
__global__ void __launch_bounds__(256) final_kernel(const float* __restrict__ Hid,
    const float* __restrict__ g2, const float* __restrict__ b2,
    float* __restrict__ out)
{
    __shared__ float sh[8];
    int row = blockIdx.x;
    size_t off = (size_t)row*DD + threadIdx.x*4;
    float r = 1.0f - g_cum[row];
    float4 a = *(const float4*)(g_acc + off);
    float4 h = *(const float4*)(Hid + off);
    float4 o;
    o.x = a.x + r*h.x; o.y = a.y + r*h.y; o.z = a.z + r*h.z; o.w = a.w + r*h.w;
    float s = o.x+o.y+o.z+o.w;
    float mean = blockRedSum(s, sh) * (1.0f/DD);
    float sq = o.x*o.x + o.y*o.y + o.z*o.z + o.w*o.w;
    float var = blockRedSum(sq, sh) * (1.0f/DD) - mean*mean;
    float rstd = rsqrtf(fmaxf(var,0.0f) + EPSLN);
    float4 gv = *(const float4*)(g2 + threadIdx.x*4);
    float4 bv = *(const float4*)(b2 + threadIdx.x*4);
    float4 y;
    y.x = (o.x-mean)*rstd*gv.x + bv.x;
    y.y = (o.y-mean)*rstd*gv.y + bv.y;
    y.z = (o.z-mean)*rstd*gv.z + bv.z;
    y.w = (o.w-mean)*rstd*gv.w + bv.w;
    *(float4*)(out + off) = y;
}

/* ---------------- host launcher ------------------------------------------- */
extern "C" void kernel_launch(void* const* d_in, const int* in_sizes, int n_in,
                              void* d_out, int out_size)
{
    const float* x      = (const float*)d_in[0];
    const float* g1     = (const float*)d_in[1];
    const float* b1     = (const float*)d_in[2];
    const float* W_up   = (const float*)d_in[3];
    const float* b_up   = (const float*)d_in[4];
    const float* W_down = (const float*)d_in[5];
    const float* b_down = (const float*)d_in[6];
    const float* W_halt = (const float*)d_in[7];
    const float* b_halt = (const float*)d_in[8];
    const float* W_comp = (const float*)d_in[9];
    const float* b_comp = (const float*)d_in[10];
    const float* W_attn = (const float*)d_in[11];
    const float* b_attn = (const float*)d_in[12];
    const float* g2     = (const float*)d_in[13];
    const float* b2     = (const float*)d_in[14];
    float* out = (float*)d_out;

    float *bufA, *bufB, *acc, *cum;
    cudaGetSymbolAddress((void**)&bufA, g_bufA);
    cudaGetSymbolAddress((void**)&bufB, g_bufB);
    cudaGetSymbolAddress((void**)&acc,  g_acc);
    cudaGetSymbolAddress((void**)&cum,  g_cum);

    cudaMemcpyAsync(bufA, x, sizeof(float)*(size_t)ROWS*DD, cudaMemcpyDeviceToDevice, 0);
    cudaMemsetAsync(acc, 0, sizeof(float)*(size_t)ROWS*DD, 0);
    cudaMemsetAsync(cum, 0, sizeof(float)*ROWS, 0);

    float* hid = bufA;
    float* hnw = bufB;
    for(int s=0;s<4;s++){
        rowstat_kernel<<<ROWS,256>>>(hid);
        gemm_up_kernel<<<dim3(DI_/128, ROWS/128),256>>>(hid, W_up, b_up, g1, b1);
        gemm_down_kernel<<<dim3(DD/128, ROWS/128),256>>>(W_down, b_down, hid, hnw);
        scores_kernel<<<ROWS/8,256>>>(hnw, W_comp, b_comp);
        colstats_kernel<<<BB*MM,256>>>();
        memacc_kernel<<<dim3(LL/128,BB),256>>>(hnw);
        memattn_kernel<<<dim3(BB,4,4),256>>>(W_attn);
        ctxattn_kernel<<<dim3(LL/32,BB),256>>>(hnw, b_attn);
        gate_kernel<<<ROWS,256>>>(hnw, hid, W_halt, b_halt);
        float* t = hid; hid = hnw; hnw = t;
    }
    final_kernel<<<ROWS,256>>>(hid, g2, b2, out);
}

// round 3
// speedup vs baseline: 2.9408x; 2.9408x over previous
#include <cuda_runtime.h>
#include <cuda_bf16.h>
#include <math.h>
#include <stdint.h>

#define BB 4
#define LL 4096
#define DD 1024
#define DI_ 4096
#define MM 8
#define ROWS (BB*LL)          /* 16384 */
#define THRG 0.5f
#define EPSLN 1e-6f

/* ---------------- scratch (device globals; no allocations allowed) -------- */
__device__ float g_bufA[ROWS*DD];
__device__ float g_bufB[ROWS*DD];
__device__ float g_acc[ROWS*DD];
__device__ float g_cum[ROWS];
__device__ float g_scores[ROWS*MM];
__device__ int   g_flag[ROWS];
__device__ float g_colmax[BB*MM];
__device__ float g_colsum[BB*MM];
__device__ float g_mem[BB*MM*DD];
__device__ float g_mA[BB*MM*DD];
/* bf16 hi/lo operands */
__device__ __nv_bfloat16 g_Ah[(size_t)ROWS*DD];
__device__ __nv_bfloat16 g_Al[(size_t)ROWS*DD];
__device__ __nv_bfloat16 g_acth[(size_t)ROWS*DI_];
__device__ __nv_bfloat16 g_actl[(size_t)ROWS*DI_];
__device__ __nv_bfloat16 g_Wuh[(size_t)DI_*DD];   /* W_up^T  [4096,1024] */
__device__ __nv_bfloat16 g_Wul[(size_t)DI_*DD];
__device__ __nv_bfloat16 g_Wdh[(size_t)DD*DI_];   /* W_down^T [1024,4096] */
__device__ __nv_bfloat16 g_Wdl[(size_t)DD*DI_];

/* ==================== PTX helpers ========================================= */
__device__ __forceinline__ uint32_t smem_u32(const void* p){
    uint32_t a;
    asm("{ .reg .u64 t; cvta.to.shared.u64 t, %1; cvt.u32.u64 %0, t; }" : "=r"(a) : "l"(p));
    return a;
}
#define SMEM_SWIZZLE_128B(off) ((off) ^ (((off) >> 3) & 0x70))

__device__ __forceinline__ void cp16(uint32_t dst, const void* src){
    asm volatile("cp.async.cg.shared.global [%0], [%1], 16;" :: "r"(dst), "l"(src));
}
#define CP_COMMIT() asm volatile("cp.async.commit_group;" ::: "memory")
#define CP_WAIT1()  asm volatile("cp.async.wait_group 1;" ::: "memory")
#define CP_WAIT0()  asm volatile("cp.async.wait_group 0;" ::: "memory")

__device__ __forceinline__ void ldsm4(uint32_t addr, uint32_t r[4]){
    asm volatile("ldmatrix.sync.aligned.m8n8.x4.shared.b16 {%0,%1,%2,%3}, [%4];"
        : "=r"(r[0]), "=r"(r[1]), "=r"(r[2]), "=r"(r[3]) : "r"(addr));
}
__device__ __forceinline__ void mma16816(float c[4], uint32_t a0, uint32_t a1,
                                         uint32_t a2, uint32_t a3,
                                         uint32_t b0, uint32_t b1){
    asm volatile("mma.sync.aligned.m16n8k16.row.col.f32.bf16.bf16.f32 "
        "{%0,%1,%2,%3}, {%4,%5,%6,%7}, {%8,%9}, {%0,%1,%2,%3};"
        : "+f"(c[0]), "+f"(c[1]), "+f"(c[2]), "+f"(c[3])
        : "r"(a0), "r"(a1), "r"(a2), "r"(a3), "r"(b0), "r"(b1));
}

/* ---------------- reduction helpers -------------------------------------- */
__device__ __forceinline__ float warpRedSum(float v){
#pragma unroll
    for(int o=16;o>0;o>>=1) v += __shfl_xor_sync(0xffffffffu, v, o);
    return v;
}
__device__ __forceinline__ float warpRedMax(float v){
#pragma unroll
    for(int o=16;o>0;o>>=1) v = fmaxf(v, __shfl_xor_sync(0xffffffffu, v, o));
    return v;
}
__device__ float blockRedSum(float v, float* sh){
    int lane = threadIdx.x & 31, w = threadIdx.x >> 5;
    v = warpRedSum(v);
    __syncthreads();
    if(lane==0) sh[w] = v;
    __syncthreads();
    if(threadIdx.x==0){
        float r = sh[0];
#pragma unroll
        for(int i=1;i<8;i++) r += sh[i];
        sh[0] = r;
    }
    __syncthreads();
    return sh[0];
}
__device__ float blockRedMax(float v, float* sh){
    int lane = threadIdx.x & 31, w = threadIdx.x >> 5;
    v = warpRedMax(v);
    __syncthreads();
    if(lane==0) sh[w] = v;
    __syncthreads();
    if(threadIdx.x==0){
        float r = sh[0];
#pragma unroll
        for(int i=1;i<8;i++) r = fmaxf(r, sh[i]);
        sh[0] = r;
    }
    __syncthreads();
    return sh[0];
}

/* ------ weight transpose + bf16 hi/lo split: T[n][k] = W[k][n] ------------ */
__global__ void __launch_bounds__(256) wsplit_kernel(const float* __restrict__ W,
    int K, int N, __nv_bfloat16* __restrict__ Th, __nv_bfloat16* __restrict__ Tl)
{
    __shared__ float t[32][33];
    int x = blockIdx.x*32, y = blockIdx.y*32;
    int tx = threadIdx.x & 31, ty = threadIdx.x >> 5;
#pragma unroll
    for(int j=0;j<32;j+=8) t[ty+j][tx] = W[(size_t)(y+ty+j)*N + x + tx];
    __syncthreads();
#pragma unroll
    for(int j=0;j<32;j+=8){
        float v = t[tx][ty+j];
        int n = x + ty + j, k = y + tx;
        __nv_bfloat16 h = __float2bfloat16(v);
        Th[(size_t)n*K + k] = h;
        Tl[(size_t)n*K + k] = __float2bfloat16(v - __bfloat162float(h));
    }
}

/* ------ per-row LN stats + entropy flag + emit LN'd bf16 hi/lo A ---------- */
__global__ void __launch_bounds__(256) rowstat_kernel(const float* __restrict__ X,
    const float* __restrict__ g1, const float* __restrict__ b1,
    __nv_bfloat16* __restrict__ Ah, __nv_bfloat16* __restrict__ Al)
{
    __shared__ float sh[8];
    int row = blockIdx.x;
    const float4 x4 = *((const float4*)(X + (size_t)row*DD) + threadIdx.x);
    float s = x4.x + x4.y + x4.z + x4.w;
    float mean = blockRedSum(s, sh) * (1.0f/DD);
    float sq = x4.x*x4.x + x4.y*x4.y + x4.z*x4.z + x4.w*x4.w;
    float var = blockRedSum(sq, sh) * (1.0f/DD) - mean*mean;
    float rstd = rsqrtf(fmaxf(var, 0.0f) + EPSLN);
    float mx = fmaxf(fmaxf(x4.x,x4.y), fmaxf(x4.z,x4.w));
    mx = blockRedMax(mx, sh);
    float e0=expf(x4.x-mx), e1=expf(x4.y-mx), e2=expf(x4.z-mx), e3=expf(x4.w-mx);
    float se  = e0+e1+e2+e3;
    float sxe = e0*x4.x + e1*x4.y + e2*x4.z + e3*x4.w;
    se  = blockRedSum(se, sh);
    sxe = blockRedSum(sxe, sh);
    if(threadIdx.x==0){
        float logZ = mx + logf(se);
        float ent = (logZ - sxe/se) * (1.0f/logf((float)DD));
        g_flag[row] = (ent > THRG) ? 1 : 0;
    }
    int k0 = threadIdx.x*4;
    float4 gv = *(const float4*)(g1 + k0);
    float4 bv = *(const float4*)(b1 + k0);
    float a[4];
    a[0] = (x4.x-mean)*rstd*gv.x + bv.x;
    a[1] = (x4.y-mean)*rstd*gv.y + bv.y;
    a[2] = (x4.z-mean)*rstd*gv.z + bv.z;
    a[3] = (x4.w-mean)*rstd*gv.w + bv.w;
    __nv_bfloat16 h[4], l[4];
#pragma unroll
    for(int j=0;j<4;j++){
        h[j] = __float2bfloat16(a[j]);
        l[j] = __float2bfloat16(a[j] - __bfloat162float(h[j]));
    }
    size_t off = (size_t)row*DD + k0;
    *(__nv_bfloat162*)(Ah+off)   = __nv_bfloat162(h[0],h[1]);
    *(__nv_bfloat162*)(Ah+off+2) = __nv_bfloat162(h[2],h[3]);
    *(__nv_bfloat162*)(Al+off)   = __nv_bfloat162(l[0],l[1]);
    *(__nv_bfloat162*)(Al+off+2) = __nv_bfloat162(l[2],l[3]);
}

/* ==================== mma.sync bf16 GEMM ==================================
   C[M, Ntot] = A[M,K] * B^T with 3-term bf16 split (AhBh + AhBl + AlBh).
   CTA tile 128x128, warp tile 64x32, k-chunk 64, 2-stage cp.async.
   EPI==0: up (bias + exact GELU -> bf16 hi/lo, Ntot=4096)
   EPI==1: down (bias + residual -> fp32, Ntot=1024)                        */
#define STAGE_BYTES 32768          /* A 16KB + B 16KB */
#define SMEMSZ      65536

template<int KDIM, int EPI>
__global__ void __launch_bounds__(256,2) gemm_mma(
    const __nv_bfloat16* __restrict__ Ah, const __nv_bfloat16* __restrict__ Al,
    const __nv_bfloat16* __restrict__ Bh, const __nv_bfloat16* __restrict__ Bl,
    const float* __restrict__ bias,
    const float* __restrict__ Hin, float* __restrict__ Hout,
    __nv_bfloat16* __restrict__ Oh, __nv_bfloat16* __restrict__ Ol)
{
    extern __shared__ char smem[];
    uint32_t sb = smem_u32(smem);
    const int tid  = threadIdx.x;
    const int lane = tid & 31;
    const int warp = tid >> 5;
    const int wm = warp >> 2;          /* 0..1 : 64-row slab   */
    const int wn = warp & 3;           /* 0..3 : 32-col slab   */
    const int mBase = blockIdx.y*128, nBase = blockIdx.x*128;
    constexpr int KCH = KDIM/64;
    constexpr int NKC = KCH*3;
    constexpr int NTOT = (EPI==0) ? DI_ : DD;

    float acc[4][4][4];
#pragma unroll
    for(int i=0;i<4;i++)
#pragma unroll
        for(int j=0;j<4;j++)
#pragma unroll
            for(int q=0;q<4;q++) acc[i][j][q]=0.0f;

    auto load_chunk = [&](int ck, int st){
        int p  = ck / KCH;
        int kk = (ck % KCH)*64;
        const __nv_bfloat16* Aptr = (p==2) ? Al : Ah;
        const __nv_bfloat16* Bptr = (p==1) ? Bl : Bh;
        uint32_t ab = sb + st*STAGE_BYTES;
        uint32_t bb = ab + 16384;
#pragma unroll
        for(int i=0;i<4;i++){
            int idx = tid + i*256;
            int row = idx>>3, g = idx&7;
            uint32_t soff = SMEM_SWIZZLE_128B((uint32_t)(row*128 + g*16));
            cp16(ab + soff, Aptr + (size_t)(mBase+row)*KDIM + kk + g*8);
            cp16(bb + soff, Bptr + (size_t)(nBase+row)*KDIM + kk + g*8);
        }
    };

    /* ldmatrix lane-address components (fixed per thread) */
    const int a_lrow = lane & 15;            /* m within frag */
    const int a_lk   = (lane >> 4) * 8;      /* k half        */
    const int b_nrow = (lane & 7) + ((lane >> 4) * 8);
    const int b_bk   = ((lane >> 3) & 1) * 8;

    load_chunk(0, 0); CP_COMMIT();

    for(int ck=0; ck<NKC; ck++){
        int st = ck & 1;
        if(ck+1 < NKC){ load_chunk(ck+1, st^1); CP_COMMIT(); CP_WAIT1(); }
        else          { CP_WAIT0(); }
        __syncthreads();

        uint32_t aB = sb + st*STAGE_BYTES;
        uint32_t bB = aB + 16384;
#pragma unroll
        for(int k16=0;k16<4;k16++){
            uint32_t a[4][4];
#pragma unroll
            for(int i=0;i<4;i++){
                uint32_t off = (uint32_t)((wm*64 + i*16 + a_lrow)*128 + (k16*16 + a_lk)*2);
                ldsm4(aB + SMEM_SWIZZLE_128B(off), a[i]);
            }
            uint32_t b[2][4];
#pragma unroll
            for(int j2=0;j2<2;j2++){
                uint32_t off = (uint32_t)((wn*32 + j2*16 + b_nrow)*128 + (k16*16 + b_bk)*2);
                ldsm4(bB + SMEM_SWIZZLE_128B(off), b[j2]);
            }
#pragma unroll
            for(int i=0;i<4;i++)
#pragma unroll
                for(int j=0;j<4;j++)
                    mma16816(acc[i][j], a[i][0], a[i][1], a[i][2], a[i][3],
                             b[j>>1][(j&1)*2], b[j>>1][(j&1)*2+1]);
        }
        __syncthreads();
    }

    /* epilogue */
    const float S2 = 0.70710678118654752440f;
#pragma unroll
    for(int i=0;i<4;i++){
        int row0 = mBase + wm*64 + i*16 + (lane>>2);
#pragma unroll
        for(int j=0;j<4;j++){
            int col = nBase + wn*32 + j*8 + (lane&3)*2;
            float bx = bias[col], by = bias[col+1];
#pragma unroll
            for(int h=0;h<2;h++){
                int row = row0 + h*8;
                float v0 = acc[i][j][h*2]   + bx;
                float v1 = acc[i][j][h*2+1] + by;
                size_t off = (size_t)row*NTOT + col;
                if(EPI==0){
                    float q0 = 0.5f*v0*(1.0f+erff(v0*S2));
                    float q1 = 0.5f*v1*(1.0f+erff(v1*S2));
                    __nv_bfloat16 h0 = __float2bfloat16(q0);
                    __nv_bfloat16 h1 = __float2bfloat16(q1);
                    __nv_bfloat16 l0 = __float2bfloat16(q0 - __bfloat162float(h0));
                    __nv_bfloat16 l1 = __float2bfloat16(q1 - __bfloat162float(h1));
                    *(__nv_bfloat162*)(Oh+off) = __nv_bfloat162(h0,h1);
                    *(__nv_bfloat162*)(Ol+off) = __nv_bfloat162(l0,l1);
                } else {
                    float2 hv = *(const float2*)(Hin + off);
                    float2 o; o.x = v0 + hv.x; o.y = v1 + hv.y;
                    *(float2*)(Hout + off) = o;
                }
            }
        }
    }
}

/* ------------- scores = h_new @ W_comp + b_comp  [ROWS, 8] ---------------- */
__global__ void __launch_bounds__(256) scores_kernel(const float* __restrict__ H,
    const float* __restrict__ Wc, const float* __restrict__ bc)
{
    __shared__ float sW[DD*9];
    for(int i=threadIdx.x;i<DD*8;i+=256){ int k=i>>3, m=i&7; sW[k*9+m]=Wc[i]; }
    __syncthreads();
    int warp = threadIdx.x>>5, lane = threadIdx.x&31;
    int row = blockIdx.x*8 + warp;
    const float* hr = H + (size_t)row*DD;
    float acc[8] = {0,0,0,0,0,0,0,0};
    for(int k=lane;k<DD;k+=32){
        float x = hr[k];
#pragma unroll
        for(int m=0;m<8;m++) acc[m] += x*sW[k*9+m];
    }
#pragma unroll
    for(int m=0;m<8;m++) acc[m] = warpRedSum(acc[m]);
    if(lane==0){
#pragma unroll
        for(int m=0;m<8;m++) g_scores[(size_t)row*8+m] = acc[m] + bc[m];
    }
}

/* ------------- column softmax stats over L, zero memory/mA --------------- */
__global__ void __launch_bounds__(256) colstats_kernel(){
    __shared__ float sh[8];
    int c = blockIdx.x; int b = c>>3, m = c&7;
    const float* sc = g_scores + (size_t)b*LL*8 + m;
    float v[16];
#pragma unroll
    for(int i=0;i<16;i++) v[i] = sc[(size_t)(threadIdx.x + i*256)*8];
    float mx = -1e30f;
#pragma unroll
    for(int i=0;i<16;i++) mx = fmaxf(mx, v[i]);
    mx = blockRedMax(mx, sh);
    float se = 0.0f;
#pragma unroll
    for(int i=0;i<16;i++) se += expf(v[i]-mx);
    se = blockRedSum(se, sh);
    if(threadIdx.x==0){ g_colmax[c]=mx; g_colsum[c]=se; }
    float4 z = {0,0,0,0};
    ((float4*)(g_mem + (size_t)c*DD))[threadIdx.x] = z;
    ((float4*)(g_mA  + (size_t)c*DD))[threadIdx.x] = z;
}

/* ------------- memory[b,m,:] += sum_l P[l,m] * h[l,:] --------------------- */
__global__ void __launch_bounds__(256) memacc_kernel(const float* __restrict__ H){
    __shared__ float sp[128*8];
    int b = blockIdx.y; int lb = blockIdx.x*128;
    if(threadIdx.x<128){
        int l = lb + threadIdx.x;
#pragma unroll
        for(int m=0;m<8;m++){
            int c = b*8+m;
            sp[threadIdx.x*8+m] = expf(g_scores[((size_t)b*LL+l)*8+m]-g_colmax[c]) / g_colsum[c];
        }
    }
    __syncthreads();
    float4 acc[8];
#pragma unroll
    for(int m=0;m<8;m++){ acc[m].x=0;acc[m].y=0;acc[m].z=0;acc[m].w=0; }
    const float4* hb = (const float4*)(H + ((size_t)b*LL+lb)*DD) + threadIdx.x;
    for(int l=0;l<128;l++){
        float4 h = hb[(size_t)l*(DD/4)];
#pragma unroll
        for(int m=0;m<8;m++){
            float p = sp[l*8+m];
            acc[m].x += p*h.x; acc[m].y += p*h.y; acc[m].z += p*h.z; acc[m].w += p*h.w;
        }
    }
    int d0 = threadIdx.x*4;
#pragma unroll
    for(int m=0;m<8;m++){
        float* mp = g_mem + ((size_t)b*8+m)*DD + d0;
        atomicAdd(mp+0,acc[m].x); atomicAdd(mp+1,acc[m].y);
        atomicAdd(mp+2,acc[m].z); atomicAdd(mp+3,acc[m].w);
    }
}

/* ------------- mA[b,m,:] = memory[b,m,:] @ W_attn ------------------------- */
__global__ void __launch_bounds__(256) memattn_kernel(const float* __restrict__ Wa){
    __shared__ float sM[8][256];
    int b  = blockIdx.x;
    int nb = blockIdx.y*256;
    int ks = blockIdx.z*256;
    for(int i=threadIdx.x;i<8*256;i+=256){
        int m=i>>8, k=i&255;
        sM[m][k] = g_mem[((size_t)b*8+m)*DD + ks + k];
    }
    __syncthreads();
    int n = nb + threadIdx.x;
    float acc[8] = {0,0,0,0,0,0,0,0};
    for(int k=0;k<256;k++){
        float w = Wa[(size_t)(ks+k)*DD + n];
#pragma unroll
        for(int m=0;m<8;m++) acc[m] += sM[m][k]*w;
    }
#pragma unroll
    for(int m=0;m<8;m++) atomicAdd(&g_mA[((size_t)b*8+m)*DD+n], acc[m]);
}

/* ------------- h_new += softmax_m(scores) @ mA + b_attn ------------------- */
__global__ void __launch_bounds__(256) ctxattn_kernel(float* __restrict__ H,
    const float* __restrict__ ba)
{
    __shared__ float sMA[8*DD];
    __shared__ float sp[32*8];
    int b = blockIdx.y; int rb = blockIdx.x*32;
    for(int i=threadIdx.x;i<8*DD;i+=256) sMA[i] = g_mA[(size_t)b*8*DD + i];
    if(threadIdx.x<32){
        int l = rb + threadIdx.x;
        float s[8]; float mx = -1e30f;
#pragma unroll
        for(int m=0;m<8;m++){ s[m]=g_scores[((size_t)b*LL+l)*8+m]; mx=fmaxf(mx,s[m]); }
        float se=0.0f;
#pragma unroll
        for(int m=0;m<8;m++){ s[m]=expf(s[m]-mx); se+=s[m]; }
        float inv = 1.0f/se;
#pragma unroll
        for(int m=0;m<8;m++) sp[threadIdx.x*8+m] = s[m]*inv;
    }
    __syncthreads();
    int d0 = threadIdx.x*4;
    float4 bv = *(const float4*)(ba + d0);
    for(int r=0;r<32;r++){
        size_t off = ((size_t)b*LL + rb + r)*DD + d0;
        float4 h = *(float4*)(H + off);
#pragma unroll
        for(int m=0;m<8;m++){
            float p = sp[r*8+m];
            float4 mv = *(const float4*)(&sMA[m*DD + d0]);
            h.x += p*mv.x; h.y += p*mv.y; h.z += p*mv.z; h.w += p*mv.w;
        }
        h.x += bv.x; h.y += bv.y; h.z += bv.z; h.w += bv.w;
        *(float4*)(H + off) = h;
    }
}

/* ------------- gate (entropy) + halting + ACT accumulate ------------------ */
__global__ void __launch_bounds__(256) gate_kernel(float* __restrict__ Hn,
    const float* __restrict__ Hold,
    const float* __restrict__ Wh, const float* __restrict__ bh)
{
    __shared__ float sh[8];
    int row = blockIdx.x;
    int upd = g_flag[row];
    size_t off = (size_t)row*DD + threadIdx.x*4;
    float4 v;
    if(upd){
        v = *(const float4*)(Hn + off);
    } else {
        v = *(const float4*)(Hold + off);
        *(float4*)(Hn + off) = v;
    }
    float4 w4 = *(const float4*)(Wh + threadIdx.x*4);
    float d = v.x*w4.x + v.y*w4.y + v.z*w4.z + v.w*w4.w;
    d = blockRedSum(d, sh);
    float p = 1.0f/(1.0f + expf(-(d + bh[0])));
    float cum = g_cum[row];
    float w = p*(1.0f - cum);
    float4 a = *(float4*)(g_acc + off);
    a.x += w*v.x; a.y += w*v.y; a.z += w*v.z; a.w += w*v.w;
    *(float4*)(g_acc + off) = a;
    if(threadIdx.x==0) g_cum[row] = cum + w;
}

/* ------------- out = LN(acc + (1-cum)*hidden; g2,b2) ---------------------- */
__global__ void __launch_bounds__(256) final_kernel(const float* __restrict__ Hid,
    const float* __restrict__ g2, const float* __restrict__ b2,
    float* __restrict__ out)
{
    __shared__ float sh[8];
    int row = blockIdx.x;
    size_t off = (size_t)row*DD + threadIdx.x*4;
    float r = 1.0f - g_cum[row];
    float4 a = *(const float4*)(g_acc + off);
    float4 h = *(const float4*)(Hid + off);
    float4 o;
    o.x = a.x + r*h.x; o.y = a.y + r*h.y; o.z = a.z + r*h.z; o.w = a.w + r*h.w;
    float s = o.x+o.y+o.z+o.w;
    float mean = blockRedSum(s, sh) * (1.0f/DD);
    float sq = o.x*o.x + o.y*o.y + o.z*o.z + o.w*o.w;
    float var = blockRedSum(sq, sh) * (1.0f/DD) - mean*mean;
    float rstd = rsqrtf(fmaxf(var,0.0f) + EPSLN);
    float4 gv = *(const float4*)(g2 + threadIdx.x*4);
    float4 bv = *(const float4*)(b2 + threadIdx.x*4);
    float4 y;
    y.x = (o.x-mean)*rstd*gv.x + bv.x;
    y.y = (o.y-mean)*rstd*gv.y + bv.y;
    y.z = (o.z-mean)*rstd*gv.z + bv.z;
    y.w = (o.w-mean)*rstd*gv.w + bv.w;
    *(float4*)(out + off) = y;
}

/* ---------------- host launcher ------------------------------------------- */
extern "C" void kernel_launch(void* const* d_in, const int* in_sizes, int n_in,
                              void* d_out, int out_size)
{
    const float* x      = (const float*)d_in[0];
    const float* g1     = (const float*)d_in[1];
    const float* b1     = (const float*)d_in[2];
    const float* W_up   = (const float*)d_in[3];
    const float* b_up   = (const float*)d_in[4];
    const float* W_down = (const float*)d_in[5];
    const float* b_down = (const float*)d_in[6];
    const float* W_halt = (const float*)d_in[7];
    const float* b_halt = (const float*)d_in[8];
    const float* W_comp = (const float*)d_in[9];
    const float* b_comp = (const float*)d_in[10];
    const float* W_attn = (const float*)d_in[11];
    const float* b_attn = (const float*)d_in[12];
    const float* g2     = (const float*)d_in[13];
    const float* b2     = (const float*)d_in[14];
    float* out = (float*)d_out;

    static int attr_set = 0;
    if(!attr_set){
        cudaFuncSetAttribute((const void*)gemm_mma<1024,0>,
                             cudaFuncAttributeMaxDynamicSharedMemorySize, SMEMSZ);
        cudaFuncSetAttribute((const void*)gemm_mma<4096,1>,
                             cudaFuncAttributeMaxDynamicSharedMemorySize, SMEMSZ);
        attr_set = 1;
    }

    float *bufA, *bufB, *acc, *cum;
    __nv_bfloat16 *Ah, *Al, *acth, *actl, *Wuh, *Wul, *Wdh, *Wdl;
    cudaGetSymbolAddress((void**)&bufA, g_bufA);
    cudaGetSymbolAddress((void**)&bufB, g_bufB);
    cudaGetSymbolAddress((void**)&acc,  g_acc);
    cudaGetSymbolAddress((void**)&cum,  g_cum);
    cudaGetSymbolAddress((void**)&Ah,   g_Ah);
    cudaGetSymbolAddress((void**)&Al,   g_Al);
    cudaGetSymbolAddress((void**)&acth, g_acth);
    cudaGetSymbolAddress((void**)&actl, g_actl);
    cudaGetSymbolAddress((void**)&Wuh,  g_Wuh);
    cudaGetSymbolAddress((void**)&Wul,  g_Wul);
    cudaGetSymbolAddress((void**)&Wdh,  g_Wdh);
    cudaGetSymbolAddress((void**)&Wdl,  g_Wdl);

    cudaMemcpyAsync(bufA, x, sizeof(float)*(size_t)ROWS*DD, cudaMemcpyDeviceToDevice, 0);
    cudaMemsetAsync(acc, 0, sizeof(float)*(size_t)ROWS*DD, 0);
    cudaMemsetAsync(cum, 0, sizeof(float)*ROWS, 0);

    wsplit_kernel<<<dim3(DI_/32, DD/32),256>>>(W_up,   DD,  DI_, Wuh, Wul);
    wsplit_kernel<<<dim3(DD/32, DI_/32),256>>>(W_down, DI_, DD,  Wdh, Wdl);

    float* hid = bufA;
    float* hnw = bufB;
    for(int s=0;s<4;s++){
        rowstat_kernel<<<ROWS,256>>>(hid, g1, b1, Ah, Al);
        gemm_mma<1024,0><<<dim3(DI_/128, ROWS/128),256,SMEMSZ>>>(
            Ah, Al, Wuh, Wul, b_up, nullptr, nullptr, acth, actl);
        gemm_mma<4096,1><<<dim3(DD/128, ROWS/128),256,SMEMSZ>>>(
            acth, actl, Wdh, Wdl, b_down, hid, hnw, nullptr, nullptr);
        scores_kernel<<<ROWS/8,256>>>(hnw, W_comp, b_comp);
        colstats_kernel<<<BB*MM,256>>>();
        memacc_kernel<<<dim3(LL/128,BB),256>>>(hnw);
        memattn_kernel<<<dim3(BB,4,4),256>>>(W_attn);
        ctxattn_kernel<<<dim3(LL/32,BB),256>>>(hnw, b_attn);
        gate_kernel<<<ROWS,256>>>(hnw, hid, W_halt, b_halt);
        float* t = hid; hid = hnw; hnw = t;
    }
    final_kernel<<<ROWS,256>>>(hid, g2, b2, out);
}